// round 10
// baseline (speedup 1.0000x reference)
#include <cuda_runtime.h>

#define NB 2
#define NC 128
#define NH 64
#define NW 64
#define NG 8
#define NPIX 4096
#define HP 78
#define PP (78*78)
#define NBORD 1988   // border pixels per padded plane: 2*7*78 + 2*64*7
#define ZB 249       // ceil(NG*NBORD*4 / 256) border-zero blocks per (b, m)

// Plane-per-cq layouts:
//  Q: [(b*NG+g)*4 + cq]*NPIX + pix
//  K/V: [(b*NG+g)*4 + cq]*PP + off   (off = padded-7 coords)
__device__ float4 g_Q[NB*NG*4*NPIX];
__device__ float4 g_K[NB*NG*4*PP];
__device__ float4 g_V[NB*NG*4*PP];

// exp(x) without MUFU: runs entirely on the fma/alu pipes.
// Valid for |x| < ~85 (logits here are within +-60). Rel err ~3e-6.
__device__ __forceinline__ float fexp(float x) {
    float t = x * 1.4426950408889634f;      // log2(e)
    float z = t + 12582912.0f;              // round-to-nearest via magic
    int   i = __float_as_int(z);
    float n = z - 12582912.0f;
    float f = t - n;                        // f in [-0.5, 0.5]
    float p = 1.3333558146e-3f;             // 2^f minimax, deg 5
    p = fmaf(p, f, 9.6181291076e-3f);
    p = fmaf(p, f, 5.5504108664e-2f);
    p = fmaf(p, f, 2.4022650696e-1f);
    p = fmaf(p, f, 6.9314718056e-1f);
    p = fmaf(p, f, 1.0f);
    float s = __int_as_float((i + (127 - 0x4B400000)) << 23);  // 2^n
    return p * s;
}

// One kernel: blocks with bx<64 do the 1x1-conv GEMM; blocks with bx>=64 zero
// the 7-wide halo of the padded K/V planes (disjoint regions -> safe to fuse).
__global__ __launch_bounds__(256) void qkv_kernel(
    const float* __restrict__ fm,
    const float* __restrict__ wq,
    const float* __restrict__ wk,
    const float* __restrict__ wv)
{
    const int m = blockIdx.z;           // 0=Q, 1=K, 2=V
    const int b = blockIdx.y;
    const int bx = blockIdx.x;

    if (bx >= 64) {
        if (m == 0) return;
        int i = (bx - 64)*256 + threadIdx.x;
        if (i >= NG*NBORD*4) return;
        int cq = i & 3;
        int r = i >> 2;
        int bp = r % NBORD;
        int gg = r / NBORD;
        int off;
        if (bp < 546) {
            off = (bp / 78)*HP + (bp % 78);
        } else if (bp < 1092) {
            int q = bp - 546;
            off = (71 + q / 78)*HP + (q % 78);
        } else if (bp < 1540) {
            int q = bp - 1092;
            off = (7 + q / 7)*HP + (q % 7);
        } else {
            int q = bp - 1540;
            off = (7 + q / 7)*HP + 71 + (q % 7);
        }
        int idx = ((b*NG + gg)*4 + cq)*PP + off;
        float4 z = make_float4(0.f, 0.f, 0.f, 0.f);
        if (m == 1) g_K[idx] = z; else g_V[idx] = z;
        return;
    }

    const int pixbase = bx * 64;
    const int tid = threadIdx.x;
    const int p4 = tid & 15;
    const int og = tid >> 4;

    const float* W = (m == 0) ? wq : (m == 1) ? wk : wv;
    const float* xin = fm + ((size_t)b*2*NC + (m == 0 ? NC : 0))*NPIX + pixbase + p4*4;
    const float* Wb = W + og*8*NC;

    float acc[8][4];
    #pragma unroll
    for (int k = 0; k < 8; k++)
        acc[k][0] = acc[k][1] = acc[k][2] = acc[k][3] = 0.f;

    #pragma unroll 2
    for (int c4 = 0; c4 < 32; c4++) {
        float4 xv[4];
        #pragma unroll
        for (int cc = 0; cc < 4; cc++)
            xv[cc] = *reinterpret_cast<const float4*>(xin + (size_t)(c4*4 + cc)*NPIX);
        #pragma unroll
        for (int k = 0; k < 8; k++) {
            float4 w4 = *reinterpret_cast<const float4*>(Wb + k*NC + c4*4);
            acc[k][0] += w4.x*xv[0].x + w4.y*xv[1].x + w4.z*xv[2].x + w4.w*xv[3].x;
            acc[k][1] += w4.x*xv[0].y + w4.y*xv[1].y + w4.z*xv[2].y + w4.w*xv[3].y;
            acc[k][2] += w4.x*xv[0].z + w4.y*xv[1].z + w4.z*xv[2].z + w4.w*xv[3].z;
            acc[k][3] += w4.x*xv[0].w + w4.y*xv[1].w + w4.z*xv[2].w + w4.w*xv[3].w;
        }
    }

    const int o0 = og * 8;
    const int g = o0 >> 4;
    const int cq0 = (o0 & 15) >> 2;
    #pragma unroll
    for (int pi = 0; pi < 4; pi++) {
        int pixel = pixbase + p4*4 + pi;
        float4 v0 = make_float4(acc[0][pi], acc[1][pi], acc[2][pi], acc[3][pi]);
        float4 v1 = make_float4(acc[4][pi], acc[5][pi], acc[6][pi], acc[7][pi]);
        if (m == 0) {
            int base = ((b*NG + g)*4)*NPIX + pixel;
            g_Q[base + cq0*NPIX]       = v0;
            g_Q[base + (cq0 + 1)*NPIX] = v1;
        } else {
            int y = pixel >> 6, x = pixel & 63;
            int off = (y + 7)*HP + (x + 7);
            float4* dst = (m == 1) ? g_K : g_V;
            int base = ((b*NG + g)*4)*PP + off;
            dst[base + cq0*PP]       = v0;
            dst[base + (cq0 + 1)*PP] = v1;
        }
    }
}

// One thread per (b, g, y, x). Online raw-exp softmax in all phases:
// no logit arrays, single fused K+V pass per tap, MUFU-free exp.
__global__ __launch_bounds__(256, 2) void attn_kernel(
    const float* __restrict__ rel_h,
    const float* __restrict__ rel_w,
    float* __restrict__ out)
{
    int t = blockIdx.x * 256 + threadIdx.x;
    const int x = t & 63;
    const int y = (t >> 6) & 63;
    const int g = (t >> 12) & 7;
    const int b = t >> 15;
    const int bg = b*NG + g;
    const int pix = y*NW + x;

    const float4* __restrict__ Qp = g_Q + (size_t)bg*4*NPIX;
    const float4* __restrict__ Kp = g_K + (size_t)bg*4*PP;
    const float4* __restrict__ Vp = g_V + (size_t)bg*4*PP;

    float qa[16];
    #pragma unroll
    for (int cq = 0; cq < 4; cq++) {
        float4 qv = Qp[cq*NPIX + pix];
        qa[cq*4+0] = qv.x; qa[cq*4+1] = qv.y; qa[cq*4+2] = qv.z; qa[cq*4+3] = qv.w;
    }

    const float* rel = (g < 4) ? (rel_h + g*16*7) : (rel_w + (g - 4)*16*7);
    float bias[7];
    #pragma unroll
    for (int i = 0; i < 7; i++) {
        float s = 0.f;
        #pragma unroll
        for (int c = 0; c < 16; c++) s += qa[c] * rel[c*7 + i];
        bias[i] = s;
    }
    const bool useI = (g < 4);

    float oa[16];
    #pragma unroll
    for (int c = 0; c < 16; c++) oa[c] = 0.f;

    // ===== main 7x7: fused K+V, online raw-exp softmax =====
    {
        float ss = 0.f;
        #pragma unroll
        for (int i = 0; i < 7; i++) {
            #pragma unroll
            for (int j = 0; j < 7; j++) {
                int off = (y + 4 + i)*HP + (x + 4 + j);
                float4 k0 = Kp[0*PP + off], k1 = Kp[1*PP + off];
                float4 k2 = Kp[2*PP + off], k3 = Kp[3*PP + off];
                float d = (useI ? bias[i] : bias[j])
                    + qa[0]*k0.x  + qa[1]*k0.y  + qa[2]*k0.z  + qa[3]*k0.w
                    + qa[4]*k1.x  + qa[5]*k1.y  + qa[6]*k1.z  + qa[7]*k1.w
                    + qa[8]*k2.x  + qa[9]*k2.y  + qa[10]*k2.z + qa[11]*k2.w
                    + qa[12]*k3.x + qa[13]*k3.y + qa[14]*k3.z + qa[15]*k3.w;
                float e = fexp(d);
                ss += e;
                float4 v0 = Vp[0*PP + off], v1 = Vp[1*PP + off];
                float4 v2 = Vp[2*PP + off], v3 = Vp[3*PP + off];
                oa[0]  += e*v0.x; oa[1]  += e*v0.y; oa[2]  += e*v0.z; oa[3]  += e*v0.w;
                oa[4]  += e*v1.x; oa[5]  += e*v1.y; oa[6]  += e*v1.z; oa[7]  += e*v1.w;
                oa[8]  += e*v2.x; oa[9]  += e*v2.y; oa[10] += e*v2.z; oa[11] += e*v2.w;
                oa[12] += e*v3.x; oa[13] += e*v3.y; oa[14] += e*v3.z; oa[15] += e*v3.w;
            }
        }
        float inv = 1.0f / ss;
        #pragma unroll
        for (int c = 0; c < 16; c++) oa[c] *= inv;
    }

    // ===== refine row + col: online into temp acc, then merge =====
    #pragma unroll
    for (int phase = 0; phase < 2; phase++) {
        float r[16];
        #pragma unroll
        for (int c = 0; c < 16; c++) r[c] = 0.f;
        float ss = 0.f;
        #pragma unroll
        for (int tp = 0; tp < 15; tp++) {
            int off = (phase == 0) ? ((y + 7)*HP + (x + tp))
                                   : ((y + tp)*HP + (x + 7));
            float4 k0 = Kp[0*PP + off], k1 = Kp[1*PP + off];
            float4 k2 = Kp[2*PP + off], k3 = Kp[3*PP + off];
            float d =
                  qa[0]*k0.x  + qa[1]*k0.y  + qa[2]*k0.z  + qa[3]*k0.w
                + qa[4]*k1.x  + qa[5]*k1.y  + qa[6]*k1.z  + qa[7]*k1.w
                + qa[8]*k2.x  + qa[9]*k2.y  + qa[10]*k2.z + qa[11]*k2.w
                + qa[12]*k3.x + qa[13]*k3.y + qa[14]*k3.z + qa[15]*k3.w;
            float e = fexp(d);
            ss += e;
            float4 v0 = Vp[0*PP + off], v1 = Vp[1*PP + off];
            float4 v2 = Vp[2*PP + off], v3 = Vp[3*PP + off];
            r[0]  += e*v0.x; r[1]  += e*v0.y; r[2]  += e*v0.z; r[3]  += e*v0.w;
            r[4]  += e*v1.x; r[5]  += e*v1.y; r[6]  += e*v1.z; r[7]  += e*v1.w;
            r[8]  += e*v2.x; r[9]  += e*v2.y; r[10] += e*v2.z; r[11] += e*v2.w;
            r[12] += e*v3.x; r[13] += e*v3.y; r[14] += e*v3.z; r[15] += e*v3.w;
        }
        float inv = 1.0f / ss;
        #pragma unroll
        for (int c = 0; c < 16; c++) oa[c] += r[c] * inv;
    }

    // ===== store: out[b][g*16+c][y][x] =====
    float* ob = out + ((size_t)b*NC + g*16)*NPIX + pix;
    #pragma unroll
    for (int c = 0; c < 16; c++) ob[c*NPIX] = oa[c];
}

extern "C" void kernel_launch(void* const* d_in, const int* in_sizes, int n_in,
                              void* d_out, int out_size) {
    const float* fm = (const float*)d_in[0];
    const float* wq = (const float*)d_in[1];
    const float* wk = (const float*)d_in[2];
    const float* wv = (const float*)d_in[3];
    const float* rh = (const float*)d_in[4];
    const float* rw = (const float*)d_in[5];
    float* out = (float*)d_out;

    dim3 grid(64 + ZB, NB, 3);
    qkv_kernel<<<grid, 256>>>(fm, wq, wk, wv);

    attn_kernel<<<NB*NG*NPIX/256, 256>>>(rh, rw, out);
}

// round 11
// speedup vs baseline: 1.0835x; 1.0835x over previous
#include <cuda_runtime.h>

#define NB 2
#define NC 128
#define NH 64
#define NW 64
#define NG 8
#define NPIX 4096
#define HP 78
#define PP (78*78)
#define NBORD 1988   // border pixels per padded plane: 2*7*78 + 2*64*7
#define ZB 249       // ceil(NG*NBORD*4 / 256) border-zero blocks per (b, m)

// Plane-per-cq layouts:
//  Q: [(b*NG+g)*4 + cq]*NPIX + pix
//  K/V: [(b*NG+g)*4 + cq]*PP + off   (off = padded-7 coords)
__device__ float4 g_Q[NB*NG*4*NPIX];
__device__ float4 g_K[NB*NG*4*PP];
__device__ float4 g_V[NB*NG*4*PP];

// exp(x) without MUFU: runs entirely on the fma/alu pipes.
// Valid for |x| < ~85 (logits here are within +-60). Rel err ~3e-6.
__device__ __forceinline__ float fexp(float x) {
    float t = x * 1.4426950408889634f;      // log2(e)
    float z = t + 12582912.0f;              // round-to-nearest via magic
    int   i = __float_as_int(z);
    float n = z - 12582912.0f;
    float f = t - n;                        // f in [-0.5, 0.5]
    float p = 1.3333558146e-3f;             // 2^f minimax, deg 5
    p = fmaf(p, f, 9.6181291076e-3f);
    p = fmaf(p, f, 5.5504108664e-2f);
    p = fmaf(p, f, 2.4022650696e-1f);
    p = fmaf(p, f, 6.9314718056e-1f);
    p = fmaf(p, f, 1.0f);
    float s = __int_as_float((i + (127 - 0x4B400000)) << 23);  // 2^n
    return p * s;
}

// One kernel: blocks with bx<64 do the 1x1-conv GEMM; blocks with bx>=64 zero
// the 7-wide halo of the padded K/V planes (disjoint regions -> safe to fuse).
__global__ __launch_bounds__(256) void qkv_kernel(
    const float* __restrict__ fm,
    const float* __restrict__ wq,
    const float* __restrict__ wk,
    const float* __restrict__ wv)
{
    const int m = blockIdx.z;           // 0=Q, 1=K, 2=V
    const int b = blockIdx.y;
    const int bx = blockIdx.x;

    if (bx >= 64) {
        if (m == 0) return;
        int i = (bx - 64)*256 + threadIdx.x;
        if (i >= NG*NBORD*4) return;
        int cq = i & 3;
        int r = i >> 2;
        int bp = r % NBORD;
        int gg = r / NBORD;
        int off;
        if (bp < 546) {
            off = (bp / 78)*HP + (bp % 78);
        } else if (bp < 1092) {
            int q = bp - 546;
            off = (71 + q / 78)*HP + (q % 78);
        } else if (bp < 1540) {
            int q = bp - 1092;
            off = (7 + q / 7)*HP + (q % 7);
        } else {
            int q = bp - 1540;
            off = (7 + q / 7)*HP + 71 + (q % 7);
        }
        int idx = ((b*NG + gg)*4 + cq)*PP + off;
        float4 z = make_float4(0.f, 0.f, 0.f, 0.f);
        if (m == 1) g_K[idx] = z; else g_V[idx] = z;
        return;
    }

    const int pixbase = bx * 64;
    const int tid = threadIdx.x;
    const int p4 = tid & 15;
    const int og = tid >> 4;

    const float* W = (m == 0) ? wq : (m == 1) ? wk : wv;
    const float* xin = fm + ((size_t)b*2*NC + (m == 0 ? NC : 0))*NPIX + pixbase + p4*4;
    const float* Wb = W + og*8*NC;

    float acc[8][4];
    #pragma unroll
    for (int k = 0; k < 8; k++)
        acc[k][0] = acc[k][1] = acc[k][2] = acc[k][3] = 0.f;

    #pragma unroll 2
    for (int c4 = 0; c4 < 32; c4++) {
        float4 xv[4];
        #pragma unroll
        for (int cc = 0; cc < 4; cc++)
            xv[cc] = *reinterpret_cast<const float4*>(xin + (size_t)(c4*4 + cc)*NPIX);
        #pragma unroll
        for (int k = 0; k < 8; k++) {
            float4 w4 = *reinterpret_cast<const float4*>(Wb + k*NC + c4*4);
            acc[k][0] += w4.x*xv[0].x + w4.y*xv[1].x + w4.z*xv[2].x + w4.w*xv[3].x;
            acc[k][1] += w4.x*xv[0].y + w4.y*xv[1].y + w4.z*xv[2].y + w4.w*xv[3].y;
            acc[k][2] += w4.x*xv[0].z + w4.y*xv[1].z + w4.z*xv[2].z + w4.w*xv[3].z;
            acc[k][3] += w4.x*xv[0].w + w4.y*xv[1].w + w4.z*xv[2].w + w4.w*xv[3].w;
        }
    }

    const int o0 = og * 8;
    const int g = o0 >> 4;
    const int cq0 = (o0 & 15) >> 2;
    #pragma unroll
    for (int pi = 0; pi < 4; pi++) {
        int pixel = pixbase + p4*4 + pi;
        float4 v0 = make_float4(acc[0][pi], acc[1][pi], acc[2][pi], acc[3][pi]);
        float4 v1 = make_float4(acc[4][pi], acc[5][pi], acc[6][pi], acc[7][pi]);
        if (m == 0) {
            int base = ((b*NG + g)*4)*NPIX + pixel;
            g_Q[base + cq0*NPIX]       = v0;
            g_Q[base + (cq0 + 1)*NPIX] = v1;
        } else {
            int y = pixel >> 6, x = pixel & 63;
            int off = (y + 7)*HP + (x + 7);
            float4* dst = (m == 1) ? g_K : g_V;
            int base = ((b*NG + g)*4)*PP + off;
            dst[base + cq0*PP]       = v0;
            dst[base + (cq0 + 1)*PP] = v1;
        }
    }
}

#define SE_TAPS 28   // smem logit slots per thread (max chunk size)

// One thread per (b, g, y, x). Each softmax is done in two passes:
//  pass1: K loads -> logits -> exp -> per-thread smem slots (qa live)
//  pass2: V loads -> weighted accumulation into oa (oa live)
// This keeps the live register set ~100 so 2 blocks/SM fit at <=128 regs.
// smem slots are thread-private -> no __syncthreads needed.
__global__ __launch_bounds__(256, 2) void attn_kernel(
    const float* __restrict__ rel_h,
    const float* __restrict__ rel_w,
    float* __restrict__ out)
{
    __shared__ float se[SE_TAPS*256];

    int t = blockIdx.x * 256 + threadIdx.x;
    const int tid = threadIdx.x;
    const int x = t & 63;
    const int y = (t >> 6) & 63;
    const int g = (t >> 12) & 7;
    const int b = t >> 15;
    const int bg = b*NG + g;
    const int pix = y*NW + x;

    const float4* __restrict__ Qp = g_Q + (size_t)bg*4*NPIX;
    const float4* __restrict__ Kp = g_K + (size_t)bg*4*PP;
    const float4* __restrict__ Vp = g_V + (size_t)bg*4*PP;

    float qa[16];
    #pragma unroll
    for (int cq = 0; cq < 4; cq++) {
        float4 qv = Qp[cq*NPIX + pix];
        qa[cq*4+0] = qv.x; qa[cq*4+1] = qv.y; qa[cq*4+2] = qv.z; qa[cq*4+3] = qv.w;
    }

    const float* rel = (g < 4) ? (rel_h + g*16*7) : (rel_w + (g - 4)*16*7);
    float bias[7];
    #pragma unroll
    for (int i = 0; i < 7; i++) {
        float s = 0.f;
        #pragma unroll
        for (int c = 0; c < 16; c++) s += qa[c] * rel[c*7 + i];
        bias[i] = s;
    }
    const bool useI = (g < 4);

    float oa[16];
    #pragma unroll
    for (int c = 0; c < 16; c++) oa[c] = 0.f;

    // ===== main 7x7: two chunks (rows 0-3: 28 taps, rows 4-6: 21 taps) =====
    float ssm = 0.f;
    #pragma unroll
    for (int ch = 0; ch < 2; ch++) {
        const int i0 = (ch == 0) ? 0 : 4;
        const int ni = (ch == 0) ? 4 : 3;
        // pass1: logits -> exp -> smem
        #pragma unroll
        for (int ii = 0; ii < 4; ii++) {
            if (ii >= ni) break;
            const int i = i0 + ii;
            #pragma unroll
            for (int j = 0; j < 7; j++) {
                int off = (y + 4 + i)*HP + (x + 4 + j);
                float4 k0 = Kp[0*PP + off], k1 = Kp[1*PP + off];
                float4 k2 = Kp[2*PP + off], k3 = Kp[3*PP + off];
                float d = (useI ? bias[i] : bias[j])
                    + qa[0]*k0.x  + qa[1]*k0.y  + qa[2]*k0.z  + qa[3]*k0.w
                    + qa[4]*k1.x  + qa[5]*k1.y  + qa[6]*k1.z  + qa[7]*k1.w
                    + qa[8]*k2.x  + qa[9]*k2.y  + qa[10]*k2.z + qa[11]*k2.w
                    + qa[12]*k3.x + qa[13]*k3.y + qa[14]*k3.z + qa[15]*k3.w;
                float e = fexp(d);
                ssm += e;
                se[(ii*7 + j)*256 + tid] = e;
            }
        }
        // pass2: weighted V accumulation (unnormalized)
        #pragma unroll
        for (int ii = 0; ii < 4; ii++) {
            if (ii >= ni) break;
            const int i = i0 + ii;
            #pragma unroll
            for (int j = 0; j < 7; j++) {
                int off = (y + 4 + i)*HP + (x + 4 + j);
                float e = se[(ii*7 + j)*256 + tid];
                float4 v0 = Vp[0*PP + off], v1 = Vp[1*PP + off];
                float4 v2 = Vp[2*PP + off], v3 = Vp[3*PP + off];
                oa[0]  += e*v0.x; oa[1]  += e*v0.y; oa[2]  += e*v0.z; oa[3]  += e*v0.w;
                oa[4]  += e*v1.x; oa[5]  += e*v1.y; oa[6]  += e*v1.z; oa[7]  += e*v1.w;
                oa[8]  += e*v2.x; oa[9]  += e*v2.y; oa[10] += e*v2.z; oa[11] += e*v2.w;
                oa[12] += e*v3.x; oa[13] += e*v3.y; oa[14] += e*v3.z; oa[15] += e*v3.w;
            }
        }
    }
    {
        float inv = 1.0f / ssm;
        #pragma unroll
        for (int c = 0; c < 16; c++) oa[c] *= inv;
    }

    // ===== refine row (phase 0) + col (phase 1): two-pass each =====
    #pragma unroll
    for (int phase = 0; phase < 2; phase++) {
        float ss = 0.f;
        #pragma unroll
        for (int tp = 0; tp < 15; tp++) {
            int off = (phase == 0) ? ((y + 7)*HP + (x + tp))
                                   : ((y + tp)*HP + (x + 7));
            float4 k0 = Kp[0*PP + off], k1 = Kp[1*PP + off];
            float4 k2 = Kp[2*PP + off], k3 = Kp[3*PP + off];
            float d =
                  qa[0]*k0.x  + qa[1]*k0.y  + qa[2]*k0.z  + qa[3]*k0.w
                + qa[4]*k1.x  + qa[5]*k1.y  + qa[6]*k1.z  + qa[7]*k1.w
                + qa[8]*k2.x  + qa[9]*k2.y  + qa[10]*k2.z + qa[11]*k2.w
                + qa[12]*k3.x + qa[13]*k3.y + qa[14]*k3.z + qa[15]*k3.w;
            float e = fexp(d);
            ss += e;
            se[tp*256 + tid] = e;
        }
        float inv = 1.0f / ss;
        #pragma unroll
        for (int tp = 0; tp < 15; tp++) {
            int off = (phase == 0) ? ((y + 7)*HP + (x + tp))
                                   : ((y + tp)*HP + (x + 7));
            float w = se[tp*256 + tid] * inv;
            float4 v0 = Vp[0*PP + off], v1 = Vp[1*PP + off];
            float4 v2 = Vp[2*PP + off], v3 = Vp[3*PP + off];
            oa[0]  += w*v0.x; oa[1]  += w*v0.y; oa[2]  += w*v0.z; oa[3]  += w*v0.w;
            oa[4]  += w*v1.x; oa[5]  += w*v1.y; oa[6]  += w*v1.z; oa[7]  += w*v1.w;
            oa[8]  += w*v2.x; oa[9]  += w*v2.y; oa[10] += w*v2.z; oa[11] += w*v2.w;
            oa[12] += w*v3.x; oa[13] += w*v3.y; oa[14] += w*v3.z; oa[15] += w*v3.w;
        }
    }

    // ===== store: out[b][g*16+c][y][x] =====
    float* ob = out + ((size_t)b*NC + g*16)*NPIX + pix;
    #pragma unroll
    for (int c = 0; c < 16; c++) ob[c*NPIX] = oa[c];
}

extern "C" void kernel_launch(void* const* d_in, const int* in_sizes, int n_in,
                              void* d_out, int out_size) {
    const float* fm = (const float*)d_in[0];
    const float* wq = (const float*)d_in[1];
    const float* wk = (const float*)d_in[2];
    const float* wv = (const float*)d_in[3];
    const float* rh = (const float*)d_in[4];
    const float* rw = (const float*)d_in[5];
    float* out = (float*)d_out;

    dim3 grid(64 + ZB, NB, 3);
    qkv_kernel<<<grid, 256>>>(fm, wq, wk, wv);

    attn_kernel<<<NB*NG*NPIX/256, 256>>>(rh, rw, out);
}

// round 12
// speedup vs baseline: 1.9845x; 1.8315x over previous
#include <cuda_runtime.h>

#define NB 2
#define NC 128
#define NH 64
#define NW 64
#define NG 8
#define NPIX 4096
#define HP 78
#define PP (78*78)
#define NBORD 1988   // border pixels per padded plane: 2*7*78 + 2*64*7
#define ZB 249       // ceil(NG*NBORD*4 / 256) border-zero blocks per (b, m)

// Plane-per-cq layouts:
//  Q: [(b*NG+g)*4 + cq]*NPIX + pix
//  K/V: [(b*NG+g)*4 + cq]*PP + off   (off = padded-7 coords)
__device__ float4 g_Q[NB*NG*4*NPIX];
__device__ float4 g_K[NB*NG*4*PP];
__device__ float4 g_V[NB*NG*4*PP];

// exp(x) without MUFU: runs entirely on the fma/alu pipes.
// Valid for |x| < ~85 (logits here are within +-60). Rel err ~3e-6.
__device__ __forceinline__ float fexp(float x) {
    float t = x * 1.4426950408889634f;      // log2(e)
    float z = t + 12582912.0f;              // round-to-nearest via magic
    int   i = __float_as_int(z);
    float n = z - 12582912.0f;
    float f = t - n;                        // f in [-0.5, 0.5]
    float p = 1.3333558146e-3f;             // 2^f minimax, deg 5
    p = fmaf(p, f, 9.6181291076e-3f);
    p = fmaf(p, f, 5.5504108664e-2f);
    p = fmaf(p, f, 2.4022650696e-1f);
    p = fmaf(p, f, 6.9314718056e-1f);
    p = fmaf(p, f, 1.0f);
    float s = __int_as_float((i + (127 - 0x4B400000)) << 23);  // 2^n
    return p * s;
}

// One kernel: blocks with bx<64 do the 1x1-conv GEMM; blocks with bx>=64 zero
// the 7-wide halo of the padded K/V planes (disjoint regions -> safe to fuse).
__global__ __launch_bounds__(256) void qkv_kernel(
    const float* __restrict__ fm,
    const float* __restrict__ wq,
    const float* __restrict__ wk,
    const float* __restrict__ wv)
{
    const int m = blockIdx.z;           // 0=Q, 1=K, 2=V
    const int b = blockIdx.y;
    const int bx = blockIdx.x;

    if (bx >= 64) {
        if (m == 0) return;
        int i = (bx - 64)*256 + threadIdx.x;
        if (i >= NG*NBORD*4) return;
        int cq = i & 3;
        int r = i >> 2;
        int bp = r % NBORD;
        int gg = r / NBORD;
        int off;
        if (bp < 546) {
            off = (bp / 78)*HP + (bp % 78);
        } else if (bp < 1092) {
            int q = bp - 546;
            off = (71 + q / 78)*HP + (q % 78);
        } else if (bp < 1540) {
            int q = bp - 1092;
            off = (7 + q / 7)*HP + (q % 7);
        } else {
            int q = bp - 1540;
            off = (7 + q / 7)*HP + 71 + (q % 7);
        }
        int idx = ((b*NG + gg)*4 + cq)*PP + off;
        float4 z = make_float4(0.f, 0.f, 0.f, 0.f);
        if (m == 1) g_K[idx] = z; else g_V[idx] = z;
        return;
    }

    const int pixbase = bx * 64;
    const int tid = threadIdx.x;
    const int p4 = tid & 15;
    const int og = tid >> 4;

    const float* W = (m == 0) ? wq : (m == 1) ? wk : wv;
    const float* xin = fm + ((size_t)b*2*NC + (m == 0 ? NC : 0))*NPIX + pixbase + p4*4;
    const float* Wb = W + og*8*NC;

    float acc[8][4];
    #pragma unroll
    for (int k = 0; k < 8; k++)
        acc[k][0] = acc[k][1] = acc[k][2] = acc[k][3] = 0.f;

    #pragma unroll 2
    for (int c4 = 0; c4 < 32; c4++) {
        float4 xv[4];
        #pragma unroll
        for (int cc = 0; cc < 4; cc++)
            xv[cc] = *reinterpret_cast<const float4*>(xin + (size_t)(c4*4 + cc)*NPIX);
        #pragma unroll
        for (int k = 0; k < 8; k++) {
            float4 w4 = *reinterpret_cast<const float4*>(Wb + k*NC + c4*4);
            acc[k][0] += w4.x*xv[0].x + w4.y*xv[1].x + w4.z*xv[2].x + w4.w*xv[3].x;
            acc[k][1] += w4.x*xv[0].y + w4.y*xv[1].y + w4.z*xv[2].y + w4.w*xv[3].y;
            acc[k][2] += w4.x*xv[0].z + w4.y*xv[1].z + w4.z*xv[2].z + w4.w*xv[3].z;
            acc[k][3] += w4.x*xv[0].w + w4.y*xv[1].w + w4.z*xv[2].w + w4.w*xv[3].w;
        }
    }

    const int o0 = og * 8;
    const int g = o0 >> 4;
    const int cq0 = (o0 & 15) >> 2;
    #pragma unroll
    for (int pi = 0; pi < 4; pi++) {
        int pixel = pixbase + p4*4 + pi;
        float4 v0 = make_float4(acc[0][pi], acc[1][pi], acc[2][pi], acc[3][pi]);
        float4 v1 = make_float4(acc[4][pi], acc[5][pi], acc[6][pi], acc[7][pi]);
        if (m == 0) {
            int base = ((b*NG + g)*4)*NPIX + pixel;
            g_Q[base + cq0*NPIX]       = v0;
            g_Q[base + (cq0 + 1)*NPIX] = v1;
        } else {
            int y = pixel >> 6, x = pixel & 63;
            int off = (y + 7)*HP + (x + 7);
            float4* dst = (m == 1) ? g_K : g_V;
            int base = ((b*NG + g)*4)*PP + off;
            dst[base + cq0*PP]       = v0;
            dst[base + (cq0 + 1)*PP] = v1;
        }
    }
}

// One thread per (b, g, y-pair, x): 2 vertically-adjacent pixels, shared row
// loads. Fused K+V pass, online raw-exp softmax, MUFU-free exp. UNCAPPED regs
// (caps proved to spill in R10/R11). 128-thread blocks -> 2 blocks/SM at
// ~255 regs, all 148 SMs busy, smooth waves.
__global__ __launch_bounds__(128) void attn_kernel(
    const float* __restrict__ rel_h,
    const float* __restrict__ rel_w,
    float* __restrict__ out)
{
    int t = blockIdx.x * 128 + threadIdx.x;
    const int x  = t & 63;
    const int y2 = (t >> 6) & 31;
    const int g  = (t >> 11) & 7;
    const int b  = t >> 14;
    const int y0 = y2 * 2;
    const int bg = b*NG + g;

    const float4* __restrict__ Qp = g_Q + (size_t)bg*4*NPIX;
    const float4* __restrict__ Kp = g_K + (size_t)bg*4*PP;
    const float4* __restrict__ Vp = g_V + (size_t)bg*4*PP;

    float qa[2][16];
    #pragma unroll
    for (int py = 0; py < 2; py++) {
        int pix = (y0 + py)*NW + x;
        #pragma unroll
        for (int cq = 0; cq < 4; cq++) {
            float4 qv = Qp[cq*NPIX + pix];
            qa[py][cq*4+0] = qv.x; qa[py][cq*4+1] = qv.y;
            qa[py][cq*4+2] = qv.z; qa[py][cq*4+3] = qv.w;
        }
    }

    const float* rel = (g < 4) ? (rel_h + g*16*7) : (rel_w + (g - 4)*16*7);
    float bias[2][7];
    #pragma unroll
    for (int i = 0; i < 7; i++) {
        float s0 = 0.f, s1 = 0.f;
        #pragma unroll
        for (int c = 0; c < 16; c++) {
            float rv = rel[c*7 + i];
            s0 += qa[0][c] * rv;
            s1 += qa[1][c] * rv;
        }
        bias[0][i] = s0;
        bias[1][i] = s1;
    }
    const bool useI = (g < 4);

    float oa[2][16];
    #pragma unroll
    for (int py = 0; py < 2; py++)
        #pragma unroll
        for (int c = 0; c < 16; c++) oa[py][c] = 0.f;

    // ===== main 7x7 window: fused K+V pass, online raw-exp softmax =====
    {
        float s0 = 0.f, s1 = 0.f;
        #pragma unroll
        for (int rr = 0; rr < 8; rr++) {      // shared padded rows y0+4+rr
            #pragma unroll
            for (int j = 0; j < 7; j++) {
                int off = (y0 + 4 + rr)*HP + (x + 4 + j);
                float4 k0 = Kp[0*PP + off], k1 = Kp[1*PP + off];
                float4 k2 = Kp[2*PP + off], k3 = Kp[3*PP + off];
                float4 v0 = Vp[0*PP + off], v1 = Vp[1*PP + off];
                float4 v2 = Vp[2*PP + off], v3 = Vp[3*PP + off];
                if (rr < 7) {   // pixel 0: window row i = rr
                    float d = (useI ? bias[0][rr] : bias[0][j])
                        + qa[0][0]*k0.x + qa[0][1]*k0.y + qa[0][2]*k0.z + qa[0][3]*k0.w
                        + qa[0][4]*k1.x + qa[0][5]*k1.y + qa[0][6]*k1.z + qa[0][7]*k1.w
                        + qa[0][8]*k2.x + qa[0][9]*k2.y + qa[0][10]*k2.z + qa[0][11]*k2.w
                        + qa[0][12]*k3.x + qa[0][13]*k3.y + qa[0][14]*k3.z + qa[0][15]*k3.w;
                    float e = fexp(d);
                    s0 += e;
                    oa[0][0] += e*v0.x; oa[0][1] += e*v0.y; oa[0][2] += e*v0.z; oa[0][3] += e*v0.w;
                    oa[0][4] += e*v1.x; oa[0][5] += e*v1.y; oa[0][6] += e*v1.z; oa[0][7] += e*v1.w;
                    oa[0][8] += e*v2.x; oa[0][9] += e*v2.y; oa[0][10] += e*v2.z; oa[0][11] += e*v2.w;
                    oa[0][12] += e*v3.x; oa[0][13] += e*v3.y; oa[0][14] += e*v3.z; oa[0][15] += e*v3.w;
                }
                if (rr >= 1) {  // pixel 1: window row i = rr-1
                    float d = (useI ? bias[1][rr-1] : bias[1][j])
                        + qa[1][0]*k0.x + qa[1][1]*k0.y + qa[1][2]*k0.z + qa[1][3]*k0.w
                        + qa[1][4]*k1.x + qa[1][5]*k1.y + qa[1][6]*k1.z + qa[1][7]*k1.w
                        + qa[1][8]*k2.x + qa[1][9]*k2.y + qa[1][10]*k2.z + qa[1][11]*k2.w
                        + qa[1][12]*k3.x + qa[1][13]*k3.y + qa[1][14]*k3.z + qa[1][15]*k3.w;
                    float e = fexp(d);
                    s1 += e;
                    oa[1][0] += e*v0.x; oa[1][1] += e*v0.y; oa[1][2] += e*v0.z; oa[1][3] += e*v0.w;
                    oa[1][4] += e*v1.x; oa[1][5] += e*v1.y; oa[1][6] += e*v1.z; oa[1][7] += e*v1.w;
                    oa[1][8] += e*v2.x; oa[1][9] += e*v2.y; oa[1][10] += e*v2.z; oa[1][11] += e*v2.w;
                    oa[1][12] += e*v3.x; oa[1][13] += e*v3.y; oa[1][14] += e*v3.z; oa[1][15] += e*v3.w;
                }
            }
        }
        float inv0 = 1.0f / s0, inv1 = 1.0f / s1;
        #pragma unroll
        for (int c = 0; c < 16; c++) { oa[0][c] *= inv0; oa[1][c] *= inv1; }
    }

    // ===== refine row: per pixel, fused online pass =====
    #pragma unroll
    for (int py = 0; py < 2; py++) {
        const int row = (y0 + py + 7)*HP;
        float r[16];
        #pragma unroll
        for (int c = 0; c < 16; c++) r[c] = 0.f;
        float ss = 0.f;
        #pragma unroll
        for (int tp = 0; tp < 15; tp++) {
            int off = row + x + tp;
            float4 k0 = Kp[0*PP + off], k1 = Kp[1*PP + off];
            float4 k2 = Kp[2*PP + off], k3 = Kp[3*PP + off];
            float d =
                  qa[py][0]*k0.x + qa[py][1]*k0.y + qa[py][2]*k0.z + qa[py][3]*k0.w
                + qa[py][4]*k1.x + qa[py][5]*k1.y + qa[py][6]*k1.z + qa[py][7]*k1.w
                + qa[py][8]*k2.x + qa[py][9]*k2.y + qa[py][10]*k2.z + qa[py][11]*k2.w
                + qa[py][12]*k3.x + qa[py][13]*k3.y + qa[py][14]*k3.z + qa[py][15]*k3.w;
            float e = fexp(d);
            ss += e;
            float4 v0 = Vp[0*PP + off], v1 = Vp[1*PP + off];
            float4 v2 = Vp[2*PP + off], v3 = Vp[3*PP + off];
            r[0]  += e*v0.x; r[1]  += e*v0.y; r[2]  += e*v0.z; r[3]  += e*v0.w;
            r[4]  += e*v1.x; r[5]  += e*v1.y; r[6]  += e*v1.z; r[7]  += e*v1.w;
            r[8]  += e*v2.x; r[9]  += e*v2.y; r[10] += e*v2.z; r[11] += e*v2.w;
            r[12] += e*v3.x; r[13] += e*v3.y; r[14] += e*v3.z; r[15] += e*v3.w;
        }
        float inv = 1.0f / ss;
        #pragma unroll
        for (int c = 0; c < 16; c++) oa[py][c] += r[c] * inv;
    }

    // ===== refine col: shared rows y0..y0+15, fused online pass =====
    {
        float r0[16], r1[16];
        #pragma unroll
        for (int c = 0; c < 16; c++) { r0[c] = 0.f; r1[c] = 0.f; }
        float s0 = 0.f, s1 = 0.f;
        #pragma unroll
        for (int rr = 0; rr < 16; rr++) {
            int off = (y0 + rr)*HP + (x + 7);
            float4 k0 = Kp[0*PP + off], k1 = Kp[1*PP + off];
            float4 k2 = Kp[2*PP + off], k3 = Kp[3*PP + off];
            float4 v0 = Vp[0*PP + off], v1 = Vp[1*PP + off];
            float4 v2 = Vp[2*PP + off], v3 = Vp[3*PP + off];
            if (rr < 15) {
                float d =
                      qa[0][0]*k0.x + qa[0][1]*k0.y + qa[0][2]*k0.z + qa[0][3]*k0.w
                    + qa[0][4]*k1.x + qa[0][5]*k1.y + qa[0][6]*k1.z + qa[0][7]*k1.w
                    + qa[0][8]*k2.x + qa[0][9]*k2.y + qa[0][10]*k2.z + qa[0][11]*k2.w
                    + qa[0][12]*k3.x + qa[0][13]*k3.y + qa[0][14]*k3.z + qa[0][15]*k3.w;
                float e = fexp(d);
                s0 += e;
                r0[0]  += e*v0.x; r0[1]  += e*v0.y; r0[2]  += e*v0.z; r0[3]  += e*v0.w;
                r0[4]  += e*v1.x; r0[5]  += e*v1.y; r0[6]  += e*v1.z; r0[7]  += e*v1.w;
                r0[8]  += e*v2.x; r0[9]  += e*v2.y; r0[10] += e*v2.z; r0[11] += e*v2.w;
                r0[12] += e*v3.x; r0[13] += e*v3.y; r0[14] += e*v3.z; r0[15] += e*v3.w;
            }
            if (rr >= 1) {
                float d =
                      qa[1][0]*k0.x + qa[1][1]*k0.y + qa[1][2]*k0.z + qa[1][3]*k0.w
                    + qa[1][4]*k1.x + qa[1][5]*k1.y + qa[1][6]*k1.z + qa[1][7]*k1.w
                    + qa[1][8]*k2.x + qa[1][9]*k2.y + qa[1][10]*k2.z + qa[1][11]*k2.w
                    + qa[1][12]*k3.x + qa[1][13]*k3.y + qa[1][14]*k3.z + qa[1][15]*k3.w;
                float e = fexp(d);
                s1 += e;
                r1[0]  += e*v0.x; r1[1]  += e*v0.y; r1[2]  += e*v0.z; r1[3]  += e*v0.w;
                r1[4]  += e*v1.x; r1[5]  += e*v1.y; r1[6]  += e*v1.z; r1[7]  += e*v1.w;
                r1[8]  += e*v2.x; r1[9]  += e*v2.y; r1[10] += e*v2.z; r1[11] += e*v2.w;
                r1[12] += e*v3.x; r1[13] += e*v3.y; r1[14] += e*v3.z; r1[15] += e*v3.w;
            }
        }
        float inv0 = 1.0f / s0, inv1 = 1.0f / s1;
        #pragma unroll
        for (int c = 0; c < 16; c++) {
            oa[0][c] += r0[c] * inv0;
            oa[1][c] += r1[c] * inv1;
        }
    }

    // ===== store: out[b][g*16+c][y0+py][x] =====
    #pragma unroll
    for (int py = 0; py < 2; py++) {
        float* ob = out + ((size_t)b*NC + g*16)*NPIX + (y0 + py)*NW + x;
        #pragma unroll
        for (int c = 0; c < 16; c++) ob[c*NPIX] = oa[py][c];
    }
}

extern "C" void kernel_launch(void* const* d_in, const int* in_sizes, int n_in,
                              void* d_out, int out_size) {
    const float* fm = (const float*)d_in[0];
    const float* wq = (const float*)d_in[1];
    const float* wk = (const float*)d_in[2];
    const float* wv = (const float*)d_in[3];
    const float* rh = (const float*)d_in[4];
    const float* rw = (const float*)d_in[5];
    float* out = (float*)d_out;

    dim3 grid(64 + ZB, NB, 3);
    qkv_kernel<<<grid, 256>>>(fm, wq, wk, wv);

    attn_kernel<<<NB*NG*NW*32/128, 128>>>(rh, rw, out);
}